// round 16
// baseline (speedup 1.0000x reference)
#include <cuda_runtime.h>
#include <cuda_bf16.h>
#include <math.h>

#define N_IMG 8
#define C_CH  64
#define HW    128
#define PLANE (HW*HW)            // 16384
#define NPLANES (N_IMG*C_CH)     // 512
#define KK 9

__device__ float g4[NPLANES * 4];      // gap partials (4 segs/plane)
__device__ float g_w[NPLANES * KK];    // softmax tap weights

// ---------------------------------------------------------------------------
// Kernel 1: partial global-average-pool. 2048 CTAs, each sums a quarter plane.
// ---------------------------------------------------------------------------
__global__ void gap_kernel(const float* __restrict__ x) {
    int seg = blockIdx.x;
    const float4* p = reinterpret_cast<const float4*>(x) + (size_t)seg * 1024;
    float s = 0.f;
    #pragma unroll
    for (int k = 0; k < 4; k++) {
        float4 v = p[threadIdx.x + k * 256];
        s += (v.x + v.y) + (v.z + v.w);
    }
    #pragma unroll
    for (int o = 16; o; o >>= 1) s += __shfl_xor_sync(0xffffffffu, s, o);
    __shared__ float ws[8];
    if ((threadIdx.x & 31) == 0) ws[threadIdx.x >> 5] = s;
    __syncthreads();
    if (threadIdx.x == 0) {
        float v = ws[0] + ws[1] + ws[2] + ws[3] + ws[4] + ws[5] + ws[6] + ws[7];
        g4[seg] = v;
    }
}

// ---------------------------------------------------------------------------
// Kernel 2: weights. grid=N_IMG, block=576 (thread = (channel, tap)).
// f = gap @ conv_w.T ; BN(eval) ; softmax over 9 taps -> g_w
// ---------------------------------------------------------------------------
__global__ void weight_kernel(const float* __restrict__ conv_w,
                              const float* __restrict__ gamma,
                              const float* __restrict__ beta,
                              const float* __restrict__ mean,
                              const float* __restrict__ var) {
    __shared__ float gs[C_CH];
    __shared__ float raw[C_CH * KK];
    int n   = blockIdx.x;
    int tid = threadIdx.x;                 // 0..575
    if (tid < C_CH) {
        const float* g = &g4[(n * C_CH + tid) * 4];
        gs[tid] = (g[0] + g[1] + g[2] + g[3]) * (1.f / (float)PLANE);
    }
    __syncthreads();

    {
        int row = tid;                     // = c*9+k, output channel in [0,576)
        const float* wr = conv_w + (size_t)row * C_CH;
        float acc = 0.f;
        #pragma unroll 16
        for (int cc = 0; cc < C_CH; cc++) acc += gs[cc] * wr[cc];
        float inv = rsqrtf(var[row] + 1e-5f);
        raw[row] = (acc - mean[row]) * (gamma[row] * inv) + beta[row];
    }
    __syncthreads();

    if (tid < C_CH) {
        const float* r = &raw[tid * KK];
        float m = r[0];
        #pragma unroll
        for (int k = 1; k < KK; k++) m = fmaxf(m, r[k]);
        float e[KK], s = 0.f;
        #pragma unroll
        for (int k = 0; k < KK; k++) { e[k] = expf(r[k] - m); s += e[k]; }
        float is = 1.f / s;
        float* d = &g_w[(n * C_CH + tid) * KK];
        #pragma unroll
        for (int k = 0; k < KK; k++) d[k] = e[k] * is;
    }
}

// ---------------------------------------------------------------------------
// Kernel 3: conv. No smem, no barriers. CTA = (plane, 32-row block).
// Warp = 4 output rows; all 6 input rows preloaded (MLP 6);
// column neighbors via shuffles; writes out and x-out.
// ---------------------------------------------------------------------------
__global__ __launch_bounds__(256, 4) void conv_kernel(
        const float* __restrict__ x,
        float* __restrict__ out,
        float* __restrict__ diff) {
    int tid   = threadIdx.x;
    int lane  = tid & 31;
    int wrp   = tid >> 5;
    int plane = blockIdx.x >> 2;
    int R     = (blockIdx.x & 3) * 32 + wrp * 4;   // out rows R..R+3

    float wt[KK];
    const float* wp = g_w + plane * KK;
    #pragma unroll
    for (int k = 0; k < KK; k++) wt[k] = __ldg(&wp[k]);

    const float4* x4 = reinterpret_cast<const float4*>(x + (size_t)plane * PLANE);
    float4* out4  = reinterpret_cast<float4*>(out  + (size_t)plane * PLANE);
    float4* diff4 = reinterpret_cast<float4*>(diff + (size_t)plane * PLANE);

    // preload 6 input rows t = R-1 .. R+4 (reflect at edges)
    float4 d[6];
    #pragma unroll
    for (int i = 0; i < 6; i++) {
        int t  = R - 1 + i;
        int gr = (t < 0) ? 1 : (t > 127 ? 126 : t);
        d[i] = x4[gr * 32 + lane];
    }
    // column neighbors for each row
    float lf[6], rg[6];
    #pragma unroll
    for (int i = 0; i < 6; i++) {
        lf[i] = __shfl_up_sync(0xffffffffu, d[i].w, 1);
        rg[i] = __shfl_down_sync(0xffffffffu, d[i].x, 1);
        if (lane == 0)  lf[i] = d[i].y;    // xp col 0 = x col 1
        if (lane == 31) rg[i] = d[i].z;    // xp col 129 = x col 126
    }

    #pragma unroll
    for (int r = 0; r < 4; r++) {          // out row R+r uses input rows r..r+2
        float a0 = 0.f, a1 = 0.f, a2 = 0.f, a3 = 0.f;
        #pragma unroll
        for (int ki = 0; ki < 3; ki++) {
            int i = r + ki;
            float w0 = wt[ki * 3 + 0], w1 = wt[ki * 3 + 1], w2 = wt[ki * 3 + 2];
            a0 = fmaf(w0, lf[i],   fmaf(w1, d[i].x, fmaf(w2, d[i].y, a0)));
            a1 = fmaf(w0, d[i].x,  fmaf(w1, d[i].y, fmaf(w2, d[i].z, a1)));
            a2 = fmaf(w0, d[i].y,  fmaf(w1, d[i].z, fmaf(w2, d[i].w, a2)));
            a3 = fmaf(w0, d[i].z,  fmaf(w1, d[i].w, fmaf(w2, rg[i],  a3)));
        }
        int oi = (R + r) * 32 + lane;
        float4 c = d[r + 1];               // center row = x
        out4[oi]  = make_float4(a0, a1, a2, a3);
        diff4[oi] = make_float4(c.x - a0, c.y - a1, c.z - a2, c.w - a3);
    }
}

// ---------------------------------------------------------------------------
extern "C" void kernel_launch(void* const* d_in, const int* in_sizes, int n_in,
                              void* d_out, int out_size) {
    const float* x      = (const float*)d_in[0];
    const float* conv_w = (const float*)d_in[1];
    const float* gamma  = (const float*)d_in[2];
    const float* beta   = (const float*)d_in[3];
    const float* mean   = (const float*)d_in[4];
    const float* var    = (const float*)d_in[5];

    float* out  = (float*)d_out;
    float* diff = out + (size_t)NPLANES * PLANE;

    gap_kernel<<<NPLANES * 4, 256>>>(x);
    weight_kernel<<<N_IMG, C_CH * KK>>>(conv_w, gamma, beta, mean, var);
    conv_kernel<<<NPLANES * 4, 256>>>(x, out, diff);
}

// round 17
// speedup vs baseline: 1.7986x; 1.7986x over previous
#include <cuda_runtime.h>
#include <cuda_bf16.h>
#include <math.h>

#define N_IMG 8
#define C_CH  64
#define HW    128
#define PLANE (HW*HW)            // 16384
#define NPLANES (N_IMG*C_CH)     // 512
#define KK 9

typedef unsigned long long ull;

__device__ float g4[NPLANES * 2];      // gap partials (2 half-planes per plane)

// ---- f32x2 packed helpers (sm_103a FFMA2 path) ----
__device__ __forceinline__ ull pk(float a, float b) {
    ull r; asm("mov.b64 %0, {%1, %2};" : "=l"(r) : "f"(a), "f"(b)); return r;
}
__device__ __forceinline__ ull ffma2(ull a, ull b, ull c) {
    ull d; asm("fma.rn.f32x2 %0, %1, %2, %3;" : "=l"(d) : "l"(a), "l"(b), "l"(c)); return d;
}
__device__ __forceinline__ ull fmul2(ull a, ull b) {
    ull d; asm("mul.rn.f32x2 %0, %1, %2;" : "=l"(d) : "l"(a), "l"(b)); return d;
}

// ---------------------------------------------------------------------------
// Kernel 1: partial GAP. 1024 CTAs, each sums half a plane.
// 8 independent float4 LDGs per thread, fully unrolled (deep MLP).
// ---------------------------------------------------------------------------
__global__ __launch_bounds__(256) void gap_kernel(const float* __restrict__ x) {
    int seg = blockIdx.x;                          // plane*2 + h
    const float4* p = reinterpret_cast<const float4*>(x) + (size_t)seg * 2048;
    float4 v[8];
    #pragma unroll
    for (int k = 0; k < 8; k++) v[k] = p[threadIdx.x + k * 256];
    float s = 0.f;
    #pragma unroll
    for (int k = 0; k < 8; k++) s += (v[k].x + v[k].y) + (v[k].z + v[k].w);
    #pragma unroll
    for (int o = 16; o; o >>= 1) s += __shfl_xor_sync(0xffffffffu, s, o);
    __shared__ float ws[8];
    if ((threadIdx.x & 31) == 0) ws[threadIdx.x >> 5] = s;
    __syncthreads();
    if (threadIdx.x == 0) {
        float v0 = ws[0] + ws[1] + ws[2] + ws[3] + ws[4] + ws[5] + ws[6] + ws[7];
        g4[seg] = v0;
    }
}

// ---------------------------------------------------------------------------
// Kernel 2: warp-shuffle sliding-window conv with packed f32x2 math.
// CTA per plane (512 CTAs x 256 thr). Warp = 16 rows; lane owns 4 cols as
// two f32x2 pairs. Depth-2 pipelined row loads. Stores: STG.128.
// ---------------------------------------------------------------------------
__global__ __launch_bounds__(256, 4) void conv_kernel(
        const float* __restrict__ x,
        const float* __restrict__ conv_w,
        const float* __restrict__ gamma,
        const float* __restrict__ beta,
        const float* __restrict__ mean,
        const float* __restrict__ var,
        float* __restrict__ out,
        float* __restrict__ diff) {
    __shared__ float gs[C_CH];
    __shared__ float raw[12];
    __shared__ float wsm[12];

    int tid   = threadIdx.x;
    int lane  = tid & 31;
    int wrp   = tid >> 5;
    int plane = blockIdx.x;
    int n     = plane >> 6;
    int ch    = plane & 63;

    if (tid < C_CH) {
        const float* g = &g4[(n * C_CH + tid) * 2];
        gs[tid] = (g[0] + g[1]) * (1.f / (float)PLANE);
    }
    __syncthreads();

    // weight dots distributed over warps
    for (int row = wrp; row < KK; row += 8) {
        int grow = ch * KK + row;
        const float* wr = conv_w + (size_t)grow * C_CH;
        float part = gs[lane] * wr[lane] + gs[lane + 32] * wr[lane + 32];
        #pragma unroll
        for (int o = 16; o; o >>= 1) part += __shfl_xor_sync(0xffffffffu, part, o);
        if (lane == 0) {
            float inv = rsqrtf(var[grow] + 1e-5f);
            raw[row] = (part - mean[grow]) * (gamma[grow] * inv) + beta[grow];
        }
    }
    __syncthreads();

    // warp 0: softmax over the 9 taps
    if (tid < 32) {
        float val = (tid < KK) ? raw[tid] : -1e30f;
        float m = val;
        #pragma unroll
        for (int o = 16; o; o >>= 1) m = fmaxf(m, __shfl_xor_sync(0xffffffffu, m, o));
        float e = (tid < KK) ? expf(val - m) : 0.f;
        float ssum = e;
        #pragma unroll
        for (int o = 16; o; o >>= 1) ssum += __shfl_xor_sync(0xffffffffu, ssum, o);
        if (tid < KK) wsm[tid] = e / ssum;
    }
    __syncthreads();

    // packed weights (both halves identical)
    ull wp[KK];
    #pragma unroll
    for (int k = 0; k < KK; k++) { float w = wsm[k]; wp[k] = pk(w, w); }
    const ull negOne = pk(-1.f, -1.f);

    const float4* x4 = reinterpret_cast<const float4*>(x + (size_t)plane * PLANE);
    ulonglong2* outv  = reinterpret_cast<ulonglong2*>(out  + (size_t)plane * PLANE);
    ulonglong2* diffv = reinterpret_cast<ulonglong2*>(diff + (size_t)plane * PLANE);

    int R = wrp * 16;                      // this warp's 16 output rows
    const int NS = 18;                     // input rows R-1 .. R+16

    float4 vbuf[2];
    {
        int t0 = R - 1;  int g0 = (t0 < 0) ? 1 : t0;
        vbuf[0] = x4[g0 * 32 + lane];
        vbuf[1] = x4[R * 32 + lane];
    }

    ull aP0[3], aP1[3];                    // rotating accumulator pairs
    ull cP0[2], cP1[2];                    // center-row x pairs (for diff)

    #pragma unroll
    for (int s = 0; s < NS; s++) {         // input row t = R-1+s
        float4 v = vbuf[s & 1];
        if (s + 2 < NS) {
            int tp = R + 1 + s;
            int gp = (tp > 127) ? 126 : tp;
            vbuf[s & 1] = x4[gp * 32 + lane];
        }

        float lft = __shfl_up_sync(0xffffffffu, v.w, 1);
        float rgt = __shfl_down_sync(0xffffffffu, v.x, 1);
        if (lane == 0)  lft = v.y;         // xp col 0 = x col 1
        if (lane == 31) rgt = v.z;         // xp col 129 = x col 126

        // packed operand pairs: cols {c0,c1} and {c2,c3}
        ull A0 = pk(v.x, v.y);
        ull A1 = pk(v.z, v.w);
        ull PM = pk(lft, v.x);
        ull MD = pk(v.y, v.z);
        ull PR = pk(v.w, rgt);

        if (s < 16) {                      // weight row 0 for out row s
            int sl = s % 3;
            aP0[sl] = ffma2(wp[0], PM, ffma2(wp[1], A0, fmul2(wp[2], MD)));
            aP1[sl] = ffma2(wp[0], MD, ffma2(wp[1], A1, fmul2(wp[2], PR)));
        }
        if (s >= 1 && s <= 16) {           // weight row 1 for out row s-1
            int sl = (s - 1) % 3;
            int cs = (s - 1) & 1;
            aP0[sl] = ffma2(wp[3], PM, ffma2(wp[4], A0, ffma2(wp[5], MD, aP0[sl])));
            aP1[sl] = ffma2(wp[3], MD, ffma2(wp[4], A1, ffma2(wp[5], PR, aP1[sl])));
            cP0[cs] = A0;  cP1[cs] = A1;
        }
        if (s >= 2) {                      // weight row 2 for out row s-2; emit
            int sl = (s - 2) % 3;
            int cs = (s - 2) & 1;
            ull o0 = ffma2(wp[6], PM, ffma2(wp[7], A0, ffma2(wp[8], MD, aP0[sl])));
            ull o1 = ffma2(wp[6], MD, ffma2(wp[7], A1, ffma2(wp[8], PR, aP1[sl])));
            ull d0 = ffma2(o0, negOne, cP0[cs]);
            ull d1 = ffma2(o1, negOne, cP1[cs]);
            int oi = (R + s - 2) * 32 + lane;
            ulonglong2 ov; ov.x = o0; ov.y = o1;
            ulonglong2 dv; dv.x = d0; dv.y = d1;
            outv[oi]  = ov;
            diffv[oi] = dv;
        }
    }
}

// ---------------------------------------------------------------------------
extern "C" void kernel_launch(void* const* d_in, const int* in_sizes, int n_in,
                              void* d_out, int out_size) {
    const float* x      = (const float*)d_in[0];
    const float* conv_w = (const float*)d_in[1];
    const float* gamma  = (const float*)d_in[2];
    const float* beta   = (const float*)d_in[3];
    const float* mean   = (const float*)d_in[4];
    const float* var    = (const float*)d_in[5];

    float* out  = (float*)d_out;
    float* diff = out + (size_t)NPLANES * PLANE;

    gap_kernel<<<NPLANES * 2, 256>>>(x);
    conv_kernel<<<NPLANES, 256>>>(x, conv_w, gamma, beta, mean, var, out, diff);
}